// round 7
// baseline (speedup 1.0000x reference)
#include <cuda_runtime.h>
#include <cuda_fp16.h>
#include <math.h>
#include <stdint.h>

#define H 1024
#define F 2048
#define E 8
#define T 2048

// ---- gemm1 tiles ----
#define BM 128
#define BN 64
#define BK1 64
// ---- gemm2 tiles ----
#define BM2 128
#define BN2 128
#define BK2 64
#define SPH 72   // row stride (halfs) = 144B: 16B-aligned, banks 4r%32 distinct -> conflict-free

// gemm1 smem layout (halfs): A[2][128*72], B1[2][64*72], B3[2][64*72]
#define G1_A(s)   ((s) * (BM * SPH))
#define G1_B1(s)  (2 * BM * SPH + (s) * (BN * SPH))
#define G1_B3(s)  (2 * BM * SPH + 2 * BN * SPH + (s) * (BN * SPH))
#define G1_BYTES  ((2 * BM * SPH + 4 * BN * SPH) * 2)      // 73728
// gemm2 smem layout (halfs): A[2][128*72], B[2][128*72]
#define G2_A(s)   ((s) * (BM2 * SPH))
#define G2_B(s)   (2 * BM2 * SPH + (s) * (BN2 * SPH))
#define G2_BYTES  ((4 * BM2 * SPH) * 2)                    // 73728

// ---- scratch (device globals: allocation-free per harness rules) ----
__device__ int    g_cnt[E];
__device__ int    g_tok[E * T];
__device__ float  g_wgt[E * T];
__device__ __half g_mid[(size_t)E * T * F];   // [E][T][F] fp16 compacted per-expert rows

// ---------------------------------------------------------------
__device__ __forceinline__ void ldsm4(unsigned r[4], const __half* p) {
    unsigned a = (unsigned)__cvta_generic_to_shared(p);
    asm volatile("ldmatrix.sync.aligned.m8n8.x4.shared.b16 {%0,%1,%2,%3}, [%4];"
                 : "=r"(r[0]), "=r"(r[1]), "=r"(r[2]), "=r"(r[3]) : "r"(a));
}
__device__ __forceinline__ void mma16(float c[4], const unsigned a[4], unsigned b0, unsigned b1) {
    asm volatile(
        "mma.sync.aligned.m16n8k16.row.col.f32.f16.f16.f32 "
        "{%0,%1,%2,%3},{%4,%5,%6,%7},{%8,%9},{%0,%1,%2,%3};"
        : "+f"(c[0]), "+f"(c[1]), "+f"(c[2]), "+f"(c[3])
        : "r"(a[0]), "r"(a[1]), "r"(a[2]), "r"(a[3]), "r"(b0), "r"(b1));
}
__device__ __forceinline__ uint2 f4h(float4 v) {
    __half2 lo = __floats2half2_rn(v.x, v.y);
    __half2 hi = __floats2half2_rn(v.z, v.w);
    uint2 r;
    r.x = *(unsigned*)&lo; r.y = *(unsigned*)&hi;
    return r;
}
__device__ __forceinline__ void cp_async16(const __half* sdst, const __half* gsrc) {
    unsigned d = (unsigned)__cvta_generic_to_shared(sdst);
    asm volatile("cp.async.cg.shared.global [%0], [%1], 16;" :: "r"(d), "l"(gsrc));
}
#define CP_COMMIT() asm volatile("cp.async.commit_group;" ::: "memory")
#define CP_WAIT0()  asm volatile("cp.async.wait_group 0;" ::: "memory")

// ---------------------------------------------------------------
__global__ void zero_cnt_kernel() {
    if (threadIdx.x < E) g_cnt[threadIdx.x] = 0;
}

// ---------------------------------------------------------------
// Router: one warp per token.
__global__ __launch_bounds__(256) void router_kernel(
    const float* __restrict__ x, const float* __restrict__ gw,
    float* __restrict__ logits_out)
{
    const int t    = blockIdx.x * 8 + (threadIdx.x >> 5);
    const int lane = threadIdx.x & 31;
    const float4* xr  = (const float4*)(x + (size_t)t * H);
    const float4* gw4 = (const float4*)gw;

    float acc[E];
#pragma unroll
    for (int e = 0; e < E; e++) acc[e] = 0.f;

#pragma unroll
    for (int i = 0; i < 8; i++) {
        float4 xv = xr[i * 32 + lane];
#pragma unroll
        for (int e = 0; e < E; e++) {
            float4 g = gw4[e * 256 + i * 32 + lane];
            acc[e] += xv.x * g.x + xv.y * g.y + xv.z * g.z + xv.w * g.w;
        }
    }
#pragma unroll
    for (int e = 0; e < E; e++)
#pragma unroll
        for (int o = 16; o > 0; o >>= 1)
            acc[e] += __shfl_xor_sync(0xffffffffu, acc[e], o);

    if (lane == 0) {
        if (logits_out)
#pragma unroll
            for (int e = 0; e < E; e++) logits_out[(size_t)t * E + e] = acc[e];
        int i1 = 0;
#pragma unroll
        for (int e = 1; e < E; e++) if (acc[e] > acc[i1]) i1 = e;
        int i2 = -1;
#pragma unroll
        for (int e = 0; e < E; e++) {
            if (e == i1) continue;
            if (i2 < 0 || acc[e] > acc[i2]) i2 = e;
        }
        float wa = 1.f / (1.f + expf(acc[i2] - acc[i1]));
        float wb = 1.f - wa;
        int s1 = atomicAdd(&g_cnt[i1], 1);
        g_tok[i1 * T + s1] = t; g_wgt[i1 * T + s1] = wa;
        int s2 = atomicAdd(&g_cnt[i2], 1);
        g_tok[i2 * T + s2] = t; g_wgt[i2 * T + s2] = wb;
    }
}

// ---------------------------------------------------------------
// GEMM1 (fp16 mma, BK=64): mid = silu(x.w1^T) * (x.w3^T) -> g_mid fp16.
__global__ __launch_bounds__(256, 2) void gemm1_kernel(
    const float* __restrict__ x,
    const float* __restrict__ w1,
    const float* __restrict__ w3)
{
    extern __shared__ __align__(16) __half sm[];
    const int e  = blockIdx.z;
    const int n0 = blockIdx.x * BN;
    const int m0 = blockIdx.y * BM;
    const int ne = g_cnt[e];
    if (m0 >= ne) return;

    const int tid  = threadIdx.x;
    const int lane = tid & 31, wid = tid >> 5;
    const int wm   = (wid & 3) * 32, wn = (wid >> 2) * 32;

    // loader mapping: row = (tid>>4) + 16r, col4 = (tid&15)*4
    const int lrow = tid >> 4, lc = (tid & 15) * 4;

    int tokid[8];
#pragma unroll
    for (int r = 0; r < 8; r++) {
        int m = m0 + lrow + 16 * r;
        tokid[r] = g_tok[e * T + ((m < ne) ? m : (ne - 1))];
    }
    const float* b1base = w1 + ((size_t)e * F + n0 + lrow) * H + lc;
    const float* b3base = w3 + ((size_t)e * F + n0 + lrow) * H + lc;

    float acc1[2][4][4] = {}, acc3[2][4][4] = {};
    float4 va[4], vb1[2], vb3[2];

    // ---- prologue: fill stage 0 (both waves) ----
#pragma unroll
    for (int w = 0; w < 2; w++) {
#pragma unroll
        for (int r = 0; r < 4; r++)
            va[r] = *(const float4*)(x + (size_t)tokid[w * 4 + r] * H + lc);
#pragma unroll
        for (int r = 0; r < 2; r++) {
            vb1[r] = *(const float4*)(b1base + (size_t)(w * 32 + 16 * r) * H);
            vb3[r] = *(const float4*)(b3base + (size_t)(w * 32 + 16 * r) * H);
        }
#pragma unroll
        for (int r = 0; r < 4; r++)
            *(uint2*)&sm[G1_A(0) + (lrow + 16 * (w * 4 + r)) * SPH + lc] = f4h(va[r]);
#pragma unroll
        for (int r = 0; r < 2; r++) {
            *(uint2*)&sm[G1_B1(0) + (lrow + 16 * (w * 2 + r)) * SPH + lc] = f4h(vb1[r]);
            *(uint2*)&sm[G1_B3(0) + (lrow + 16 * (w * 2 + r)) * SPH + lc] = f4h(vb3[r]);
        }
    }
    __syncthreads();

    const int NC = H / BK1;  // 16
    int cur = 0;
    for (int c = 0; c < NC; c++) {
        const int  nxt  = cur ^ 1;
        const bool more = (c + 1 < NC);
        const int  k0   = (c + 1) * BK1;

        if (more) {  // wave-0 loads for next chunk
#pragma unroll
            for (int r = 0; r < 4; r++)
                va[r] = *(const float4*)(x + (size_t)tokid[r] * H + k0 + lc);
#pragma unroll
            for (int r = 0; r < 2; r++) {
                vb1[r] = *(const float4*)(b1base + (size_t)(16 * r) * H + k0);
                vb3[r] = *(const float4*)(b3base + (size_t)(16 * r) * H + k0);
            }
        }

#pragma unroll
        for (int kk = 0; kk < 32; kk += 16) {
            unsigned a[2][4];
#pragma unroll
            for (int mt = 0; mt < 2; mt++)
                ldsm4(a[mt], &sm[G1_A(cur) + (wm + mt * 16 + (lane & 15)) * SPH + kk + (lane >> 4) * 8]);
            unsigned b1f[2][4], b3f[2][4];
#pragma unroll
            for (int bh = 0; bh < 2; bh++) {
                int row = wn + bh * 16 + ((lane >> 4) & 1) * 8 + (lane & 7);
                int col = kk + ((lane >> 3) & 1) * 8;
                ldsm4(b1f[bh], &sm[G1_B1(cur) + row * SPH + col]);
                ldsm4(b3f[bh], &sm[G1_B3(cur) + row * SPH + col]);
            }
#pragma unroll
            for (int mt = 0; mt < 2; mt++)
#pragma unroll
                for (int nt = 0; nt < 4; nt++) {
                    int bh = nt >> 1, pr = (nt & 1) * 2;
                    mma16(acc1[mt][nt], a[mt], b1f[bh][pr], b1f[bh][pr + 1]);
                    mma16(acc3[mt][nt], a[mt], b3f[bh][pr], b3f[bh][pr + 1]);
                }
        }

        if (more) {  // store wave-0, load wave-1
#pragma unroll
            for (int r = 0; r < 4; r++)
                *(uint2*)&sm[G1_A(nxt) + (lrow + 16 * r) * SPH + lc] = f4h(va[r]);
#pragma unroll
            for (int r = 0; r < 2; r++) {
                *(uint2*)&sm[G1_B1(nxt) + (lrow + 16 * r) * SPH + lc] = f4h(vb1[r]);
                *(uint2*)&sm[G1_B3(nxt) + (lrow + 16 * r) * SPH + lc] = f4h(vb3[r]);
            }
#pragma unroll
            for (int r = 0; r < 4; r++)
                va[r] = *(const float4*)(x + (size_t)tokid[4 + r] * H + k0 + lc);
#pragma unroll
            for (int r = 0; r < 2; r++) {
                vb1[r] = *(const float4*)(b1base + (size_t)(32 + 16 * r) * H + k0);
                vb3[r] = *(const float4*)(b3base + (size_t)(32 + 16 * r) * H + k0);
            }
        }

#pragma unroll
        for (int kk = 32; kk < 64; kk += 16) {
            unsigned a[2][4];
#pragma unroll
            for (int mt = 0; mt < 2; mt++)
                ldsm4(a[mt], &sm[G1_A(cur) + (wm + mt * 16 + (lane & 15)) * SPH + kk + (lane >> 4) * 8]);
            unsigned b1f[2][4], b3f[2][4];
#pragma unroll
            for (int bh = 0; bh < 2; bh++) {
                int row = wn + bh * 16 + ((lane >> 4) & 1) * 8 + (lane & 7);
                int col = kk + ((lane >> 3) & 1) * 8;
                ldsm4(b1f[bh], &sm[G1_B1(cur) + row * SPH + col]);
                ldsm4(b3f[bh], &sm[G1_B3(cur) + row * SPH + col]);
            }
#pragma unroll
            for (int mt = 0; mt < 2; mt++)
#pragma unroll
                for (int nt = 0; nt < 4; nt++) {
                    int bh = nt >> 1, pr = (nt & 1) * 2;
                    mma16(acc1[mt][nt], a[mt], b1f[bh][pr], b1f[bh][pr + 1]);
                    mma16(acc3[mt][nt], a[mt], b3f[bh][pr], b3f[bh][pr + 1]);
                }
        }

        if (more) {  // store wave-1, advance
#pragma unroll
            for (int r = 0; r < 4; r++)
                *(uint2*)&sm[G1_A(nxt) + (lrow + 16 * (4 + r)) * SPH + lc] = f4h(va[r]);
#pragma unroll
            for (int r = 0; r < 2; r++) {
                *(uint2*)&sm[G1_B1(nxt) + (lrow + 16 * (2 + r)) * SPH + lc] = f4h(vb1[r]);
                *(uint2*)&sm[G1_B3(nxt) + (lrow + 16 * (2 + r)) * SPH + lc] = f4h(vb3[r]);
            }
            __syncthreads();
            cur = nxt;
        }
    }

    // ---- epilogue: SwiGLU -> g_mid (fp16) ----
    const int g = lane >> 2, tg = lane & 3;
#pragma unroll
    for (int mt = 0; mt < 2; mt++)
#pragma unroll
        for (int half = 0; half < 2; half++) {
            int m = m0 + wm + mt * 16 + g + half * 8;
            if (m >= ne) continue;
            __half* dst = g_mid + ((size_t)e * T + m) * F + n0 + wn;
#pragma unroll
            for (int nt = 0; nt < 4; nt++) {
                float h0 = acc1[mt][nt][half * 2 + 0];
                float h1 = acc1[mt][nt][half * 2 + 1];
                float g0 = acc3[mt][nt][half * 2 + 0];
                float g1 = acc3[mt][nt][half * 2 + 1];
                float r0 = h0 / (1.f + __expf(-h0)) * g0;
                float r1 = h1 / (1.f + __expf(-h1)) * g1;
                *(__half2*)(dst + nt * 8 + tg * 2) = __floats2half2_rn(r0, r1);
            }
        }
}

// ---------------------------------------------------------------
// GEMM2 (fp16 mma, BK=64): out[tok] += weight * (mid . w2^T)
__global__ __launch_bounds__(256, 2) void gemm2_kernel(
    const float* __restrict__ w2,
    float* __restrict__ out)
{
    extern __shared__ __align__(16) __half sm[];
    const int e  = blockIdx.z;
    const int n0 = blockIdx.x * BN2;
    const int m0 = blockIdx.y * BM2;
    const int ne = g_cnt[e];
    if (m0 >= ne) return;

    const int tid  = threadIdx.x;
    const int lane = tid & 31, wid = tid >> 5;
    const int wm   = (wid & 3) * 32, wn = (wid >> 2) * 64;

    const __half* amb = g_mid + ((size_t)e * T + m0) * F;
    // B loader: row = (tid>>4) + 16r, col4 = (tid&15)*4
    const int lrow = tid >> 4, lc = (tid & 15) * 4;
    const float* bbase = w2 + ((size_t)e * H + n0 + lrow) * F + lc;

    float acc[2][8][4] = {};
    float4 vB[4];

    // ---- prologue: fill stage 0 ----
#pragma unroll
    for (int i = 0; i < 4; i++) {
        int lin = i * 256 + tid;
        int row = lin >> 3, col8 = (lin & 7) * 8;
        cp_async16(&sm[G2_A(0) + row * SPH + col8], amb + (size_t)row * F + col8);
    }
    CP_COMMIT();
#pragma unroll
    for (int r = 0; r < 8; r++) {
        float4 v = *(const float4*)(bbase + (size_t)(16 * r) * F);
        *(uint2*)&sm[G2_B(0) + (lrow + 16 * r) * SPH + lc] = f4h(v);
    }
    CP_WAIT0();
    __syncthreads();

    const int NC = F / BK2;   // 32
    int cur = 0;
    for (int c = 0; c < NC; c++) {
        const int  nxt  = cur ^ 1;
        const bool more = (c + 1 < NC);
        const int  k0   = (c + 1) * BK2;

        if (more) {
#pragma unroll
            for (int i = 0; i < 4; i++) {
                int lin = i * 256 + tid;
                int row = lin >> 3, col8 = (lin & 7) * 8;
                cp_async16(&sm[G2_A(nxt) + row * SPH + col8], amb + (size_t)row * F + k0 + col8);
            }
            CP_COMMIT();
#pragma unroll
            for (int r = 0; r < 4; r++)
                vB[r] = *(const float4*)(bbase + (size_t)(16 * r) * F + k0);
        }

#pragma unroll
        for (int kk = 0; kk < 32; kk += 16) {
            unsigned a[2][4];
#pragma unroll
            for (int mt = 0; mt < 2; mt++)
                ldsm4(a[mt], &sm[G2_A(cur) + (wm + mt * 16 + (lane & 15)) * SPH + kk + (lane >> 4) * 8]);
            unsigned bf[4][4];
#pragma unroll
            for (int bh = 0; bh < 4; bh++) {
                int row = wn + bh * 16 + ((lane >> 4) & 1) * 8 + (lane & 7);
                int col = kk + ((lane >> 3) & 1) * 8;
                ldsm4(bf[bh], &sm[G2_B(cur) + row * SPH + col]);
            }
#pragma unroll
            for (int mt = 0; mt < 2; mt++)
#pragma unroll
                for (int nt = 0; nt < 8; nt++) {
                    int bh = nt >> 1, pr = (nt & 1) * 2;
                    mma16(acc[mt][nt], a[mt], bf[bh][pr], bf[bh][pr + 1]);
                }
        }

        if (more) {
#pragma unroll
            for (int r = 0; r < 4; r++)
                *(uint2*)&sm[G2_B(nxt) + (lrow + 16 * r) * SPH + lc] = f4h(vB[r]);
#pragma unroll
            for (int r = 0; r < 4; r++)
                vB[r] = *(const float4*)(bbase + (size_t)(16 * (4 + r)) * F + k0);
        }

#pragma unroll
        for (int kk = 32; kk < 64; kk += 16) {
            unsigned a[2][4];
#pragma unroll
            for (int mt = 0; mt < 2; mt++)
                ldsm4(a[mt], &sm[G2_A(cur) + (wm + mt * 16 + (lane & 15)) * SPH + kk + (lane >> 4) * 8]);
            unsigned bf[4][4];
#pragma unroll
            for (int bh = 0; bh < 4; bh++) {
                int row = wn + bh * 16 + ((lane >> 4) & 1) * 8 + (lane & 7);
                int col = kk + ((lane >> 3) & 1) * 8;
                ldsm4(bf[bh], &sm[G2_B(cur) + row * SPH + col]);
            }
#pragma unroll
            for (int mt = 0; mt < 2; mt++)
#pragma unroll
                for (int nt = 0; nt < 8; nt++) {
                    int bh = nt >> 1, pr = (nt & 1) * 2;
                    mma16(acc[mt][nt], a[mt], bf[bh][pr], bf[bh][pr + 1]);
                }
        }

        if (more) {
#pragma unroll
            for (int r = 0; r < 4; r++)
                *(uint2*)&sm[G2_B(nxt) + (lrow + 16 * (4 + r)) * SPH + lc] = f4h(vB[r]);
            CP_WAIT0();
            __syncthreads();
            cur = nxt;
        }
    }

    // ---- epilogue: weighted atomic scatter ----
    const int g = lane >> 2, tg = lane & 3;
#pragma unroll
    for (int mt = 0; mt < 2; mt++)
#pragma unroll
        for (int half = 0; half < 2; half++) {
            int m = m0 + wm + mt * 16 + g + half * 8;
            if (m >= ne) continue;
            int   tok = g_tok[e * T + m];
            float w   = g_wgt[e * T + m];
            float* dst = out + (size_t)tok * H + n0 + wn;
#pragma unroll
            for (int nt = 0; nt < 8; nt++) {
                atomicAdd(dst + nt * 8 + tg * 2 + 0, w * acc[mt][nt][half * 2 + 0]);
                atomicAdd(dst + nt * 8 + tg * 2 + 1, w * acc[mt][nt][half * 2 + 1]);
            }
        }
}

// ---------------------------------------------------------------
extern "C" void kernel_launch(void* const* d_in, const int* in_sizes, int n_in,
                              void* d_out, int out_size)
{
    const float* x  = (const float*)d_in[0];
    const float* gw = (const float*)d_in[1];
    const float* w1 = (const float*)d_in[2];
    const float* w2 = (const float*)d_in[3];
    const float* w3 = (const float*)d_in[4];
    float* out = (float*)d_out;

    // one-time attribute config (first call runs before graph capture)
    static int configured = 0;
    if (!configured) {
        cudaFuncSetAttribute(gemm1_kernel,
            cudaFuncAttributeMaxDynamicSharedMemorySize, G1_BYTES);
        cudaFuncSetAttribute(gemm2_kernel,
            cudaFuncAttributeMaxDynamicSharedMemorySize, G2_BYTES);
        configured = 1;
    }

    const size_t main_sz = (size_t)T * H;
    float* logits = ((size_t)out_size >= main_sz + (size_t)T * E)
                        ? out + main_sz : nullptr;

    cudaMemsetAsync(d_out, 0, (size_t)out_size * sizeof(float));
    zero_cnt_kernel<<<1, 32>>>();
    router_kernel<<<T / 8, 256>>>(x, gw, logits);
    gemm1_kernel<<<dim3(F / BN, T / BM, E), 256, G1_BYTES>>>(x, w1, w3);
    gemm2_kernel<<<dim3(H / BN2, T / BM2, E), 256, G2_BYTES>>>(w2, out);
}

// round 8
// speedup vs baseline: 1.3706x; 1.3706x over previous
#include <cuda_runtime.h>
#include <cuda_fp16.h>
#include <math.h>
#include <stdint.h>

#define H 1024
#define F 2048
#define E 8
#define T 2048

// ---- gemm1 tiles ----
#define BM 128
#define BN 64
#define BK 32
#define SPH 40   // smem row stride in halfs = 80B (16B-aligned); ldmatrix conflict-free

// ---- gemm2 tiles ----
#define BM2 128
#define BN2 128
#define BK2 32

// ---- scratch (device globals: allocation-free per harness rules) ----
__device__ int    g_cnt[E];
__device__ int    g_tok[E * T];
__device__ float  g_wgt[E * T];
__device__ __half g_x16[(size_t)T * H];       // fp16 copy of hidden_states
__device__ __half g_mid[(size_t)E * T * F];   // [E][T][F] fp16 compacted per-expert rows

// ---------------------------------------------------------------
__device__ __forceinline__ void ldsm4(unsigned r[4], const __half* p) {
    unsigned a = (unsigned)__cvta_generic_to_shared(p);
    asm volatile("ldmatrix.sync.aligned.m8n8.x4.shared.b16 {%0,%1,%2,%3}, [%4];"
                 : "=r"(r[0]), "=r"(r[1]), "=r"(r[2]), "=r"(r[3]) : "r"(a));
}
__device__ __forceinline__ void mma16(float c[4], const unsigned a[4], unsigned b0, unsigned b1) {
    asm volatile(
        "mma.sync.aligned.m16n8k16.row.col.f32.f16.f16.f32 "
        "{%0,%1,%2,%3},{%4,%5,%6,%7},{%8,%9},{%0,%1,%2,%3};"
        : "+f"(c[0]), "+f"(c[1]), "+f"(c[2]), "+f"(c[3])
        : "r"(a[0]), "r"(a[1]), "r"(a[2]), "r"(a[3]), "r"(b0), "r"(b1));
}
__device__ __forceinline__ uint2 f4h(float4 v) {
    __half2 lo = __floats2half2_rn(v.x, v.y);
    __half2 hi = __floats2half2_rn(v.z, v.w);
    uint2 r;
    r.x = *(unsigned*)&lo; r.y = *(unsigned*)&hi;
    return r;
}
__device__ __forceinline__ void cp_async16(const __half* sdst, const __half* gsrc) {
    unsigned d = (unsigned)__cvta_generic_to_shared(sdst);
    asm volatile("cp.async.cg.shared.global [%0], [%1], 16;" :: "r"(d), "l"(gsrc));
}
#define CP_COMMIT() asm volatile("cp.async.commit_group;" ::: "memory")
#define CP_WAIT0()  asm volatile("cp.async.wait_group 0;" ::: "memory")

// ---------------------------------------------------------------
__global__ void zero_cnt_kernel() {
    if (threadIdx.x < E) g_cnt[threadIdx.x] = 0;
}

// x fp32 -> fp16 (8 elems/thread)
__global__ __launch_bounds__(256) void xconv_kernel(const float* __restrict__ x) {
    size_t i = ((size_t)blockIdx.x * 256 + threadIdx.x) * 8;
    float4 a = *(const float4*)(x + i);
    float4 b = *(const float4*)(x + i + 4);
    uint2 ha = f4h(a), hb = f4h(b);
    *(uint4*)(g_x16 + i) = make_uint4(ha.x, ha.y, hb.x, hb.y);
}

// ---------------------------------------------------------------
// Router: one warp per token.
__global__ __launch_bounds__(256) void router_kernel(
    const float* __restrict__ x, const float* __restrict__ gw,
    float* __restrict__ logits_out)
{
    const int t    = blockIdx.x * 8 + (threadIdx.x >> 5);
    const int lane = threadIdx.x & 31;
    const float4* xr  = (const float4*)(x + (size_t)t * H);
    const float4* gw4 = (const float4*)gw;

    float acc[E];
#pragma unroll
    for (int e = 0; e < E; e++) acc[e] = 0.f;

#pragma unroll
    for (int i = 0; i < 8; i++) {
        float4 xv = xr[i * 32 + lane];
#pragma unroll
        for (int e = 0; e < E; e++) {
            float4 g = gw4[e * 256 + i * 32 + lane];
            acc[e] += xv.x * g.x + xv.y * g.y + xv.z * g.z + xv.w * g.w;
        }
    }
#pragma unroll
    for (int e = 0; e < E; e++)
#pragma unroll
        for (int o = 16; o > 0; o >>= 1)
            acc[e] += __shfl_xor_sync(0xffffffffu, acc[e], o);

    if (lane == 0) {
        if (logits_out)
#pragma unroll
            for (int e = 0; e < E; e++) logits_out[(size_t)t * E + e] = acc[e];
        int i1 = 0;
#pragma unroll
        for (int e = 1; e < E; e++) if (acc[e] > acc[i1]) i1 = e;
        int i2 = -1;
#pragma unroll
        for (int e = 0; e < E; e++) {
            if (e == i1) continue;
            if (i2 < 0 || acc[e] > acc[i2]) i2 = e;
        }
        float wa = 1.f / (1.f + expf(acc[i2] - acc[i1]));
        float wb = 1.f - wa;
        int s1 = atomicAdd(&g_cnt[i1], 1);
        g_tok[i1 * T + s1] = t; g_wgt[i1 * T + s1] = wa;
        int s2 = atomicAdd(&g_cnt[i2], 1);
        g_tok[i2 * T + s2] = t; g_wgt[i2 * T + s2] = wb;
    }
}

// ---------------------------------------------------------------
// GEMM1 (fp16 mma): mid = silu(x.w1^T) * (x.w3^T) -> g_mid fp16.
// A (gathered x rows) via cp.async from g_x16; B (w1/w3) fp32 LDG + convert.
__global__ __launch_bounds__(256, 2) void gemm1_kernel(
    const float* __restrict__ w1,
    const float* __restrict__ w3)
{
    const int e  = blockIdx.z;
    const int n0 = blockIdx.x * BN;
    const int m0 = blockIdx.y * BM;
    const int ne = g_cnt[e];
    if (m0 >= ne) return;

    __shared__ __align__(16) __half sA [2][BM * SPH];
    __shared__ __align__(16) __half sB1[2][BN * SPH];
    __shared__ __align__(16) __half sB3[2][BN * SPH];

    const int tid  = threadIdx.x;
    const int lane = tid & 31, wid = tid >> 5;
    const int wm   = (wid & 3) * 32, wn = (wid >> 2) * 32;

    // A loader (cp.async): 512 granules of 16B, 2/thread.
    //   lin = i*256 + tid, row = lin>>2 (thread's rows: tid>>2 and tid>>2+64), col8 = (lin&3)*8
    const int arow = tid >> 2, ac8 = (tid & 3) * 8;
    const __half* amp[2];
    {
        int m0r = m0 + arow;
        int m1r = m0 + arow + 64;
        int i0 = (m0r < ne) ? m0r : (ne - 1);
        int i1 = (m1r < ne) ? m1r : (ne - 1);
        amp[0] = g_x16 + (size_t)g_tok[e * T + i0] * H + ac8;
        amp[1] = g_x16 + (size_t)g_tok[e * T + i1] * H + ac8;
    }

    // B loader: row = (tid>>3) + 32r, col4 = (tid&7)*4
    const int brow = tid >> 3, bc = (tid & 7) * 4;
    const float* b1p[2];
    const float* b3p[2];
#pragma unroll
    for (int r = 0; r < 2; r++) {
        b1p[r] = w1 + ((size_t)e * F + n0 + brow + 32 * r) * H + bc;
        b3p[r] = w3 + ((size_t)e * F + n0 + brow + 32 * r) * H + bc;
    }

    float4 vb1[2], vb3[2];
    float acc1[2][4][4] = {}, acc3[2][4][4] = {};

    // ---- prologue: fill stage 0 ----
    cp_async16(&sA[0][arow * SPH + ac8],        amp[0]);
    cp_async16(&sA[0][(arow + 64) * SPH + ac8], amp[1]);
    CP_COMMIT();
#pragma unroll
    for (int r = 0; r < 2; r++) {
        vb1[r] = *(const float4*)(b1p[r]);
        vb3[r] = *(const float4*)(b3p[r]);
        *(uint2*)&sB1[0][(brow + 32 * r) * SPH + bc] = f4h(vb1[r]);
        *(uint2*)&sB3[0][(brow + 32 * r) * SPH + bc] = f4h(vb3[r]);
    }
    CP_WAIT0();
    __syncthreads();

    const int NC = H / BK;   // 32
    int cur = 0;
    for (int c = 0; c < NC; c++) {
        const int  nxt  = cur ^ 1;
        const bool more = (c + 1 < NC);
        if (more) {
            int k0 = (c + 1) * BK;
            cp_async16(&sA[nxt][arow * SPH + ac8],        amp[0] + k0);
            cp_async16(&sA[nxt][(arow + 64) * SPH + ac8], amp[1] + k0);
            CP_COMMIT();
#pragma unroll
            for (int r = 0; r < 2; r++) {
                vb1[r] = *(const float4*)(b1p[r] + k0);
                vb3[r] = *(const float4*)(b3p[r] + k0);
            }
        }

        // ---- compute on cur ----
#pragma unroll
        for (int kk = 0; kk < BK; kk += 16) {
            unsigned a[2][4];
#pragma unroll
            for (int mt = 0; mt < 2; mt++)
                ldsm4(a[mt], &sA[cur][(wm + mt * 16 + (lane & 15)) * SPH + kk + (lane >> 4) * 8]);
            unsigned b1f[2][4], b3f[2][4];
#pragma unroll
            for (int bh = 0; bh < 2; bh++) {
                int row = wn + bh * 16 + ((lane >> 4) & 1) * 8 + (lane & 7);
                int col = kk + ((lane >> 3) & 1) * 8;
                ldsm4(b1f[bh], &sB1[cur][row * SPH + col]);
                ldsm4(b3f[bh], &sB3[cur][row * SPH + col]);
            }
#pragma unroll
            for (int mt = 0; mt < 2; mt++)
#pragma unroll
                for (int nt = 0; nt < 4; nt++) {
                    int bh = nt >> 1, pr = (nt & 1) * 2;
                    mma16(acc1[mt][nt], a[mt], b1f[bh][pr], b1f[bh][pr + 1]);
                    mma16(acc3[mt][nt], a[mt], b3f[bh][pr], b3f[bh][pr + 1]);
                }
        }

        if (more) {
#pragma unroll
            for (int r = 0; r < 2; r++) {
                *(uint2*)&sB1[nxt][(brow + 32 * r) * SPH + bc] = f4h(vb1[r]);
                *(uint2*)&sB3[nxt][(brow + 32 * r) * SPH + bc] = f4h(vb3[r]);
            }
            CP_WAIT0();
            __syncthreads();
            cur = nxt;
        }
    }

    // ---- epilogue: SwiGLU -> g_mid (fp16) ----
    const int g = lane >> 2, tg = lane & 3;
#pragma unroll
    for (int mt = 0; mt < 2; mt++)
#pragma unroll
        for (int half = 0; half < 2; half++) {
            int m = m0 + wm + mt * 16 + g + half * 8;
            if (m >= ne) continue;
            __half* dst = g_mid + ((size_t)e * T + m) * F + n0 + wn;
#pragma unroll
            for (int nt = 0; nt < 4; nt++) {
                float h0 = acc1[mt][nt][half * 2 + 0];
                float h1 = acc1[mt][nt][half * 2 + 1];
                float g0 = acc3[mt][nt][half * 2 + 0];
                float g1 = acc3[mt][nt][half * 2 + 1];
                float r0 = h0 / (1.f + __expf(-h0)) * g0;
                float r1 = h1 / (1.f + __expf(-h1)) * g1;
                *(__half2*)(dst + nt * 8 + tg * 2) = __floats2half2_rn(r0, r1);
            }
        }
}

// ---------------------------------------------------------------
// GEMM2 (fp16 mma): block 128x128, warp tile 32x64, cp.async A stream.
// out[tok] += weight * (mid . w2^T)   (identical to R6)
__global__ __launch_bounds__(256, 2) void gemm2_kernel(
    const float* __restrict__ w2,
    float* __restrict__ out)
{
    const int e  = blockIdx.z;
    const int n0 = blockIdx.x * BN2;
    const int m0 = blockIdx.y * BM2;
    const int ne = g_cnt[e];
    if (m0 >= ne) return;

    __shared__ __align__(16) __half sA[2][BM2 * SPH];
    __shared__ __align__(16) __half sB[2][BN2 * SPH];

    const int tid  = threadIdx.x;
    const int lane = tid & 31, wid = tid >> 5;
    const int wm   = (wid & 3) * 32, wn = (wid >> 2) * 64;

    const __half* amb = g_mid + ((size_t)e * T + m0) * F;

    const int brow = tid >> 3, bc4 = (tid & 7) * 4;
    const float* bp[4];
#pragma unroll
    for (int r = 0; r < 4; r++)
        bp[r] = w2 + ((size_t)e * H + n0 + brow + 32 * r) * F + bc4;

    float acc[2][8][4] = {};
    float4 vB[4];

    // ---- prologue ----
#pragma unroll
    for (int i = 0; i < 2; i++) {
        int lin = i * 256 + tid;
        int row = lin >> 2, col8 = (lin & 3) * 8;
        cp_async16(&sA[0][row * SPH + col8], amb + (size_t)row * F + col8);
    }
    CP_COMMIT();
#pragma unroll
    for (int r = 0; r < 4; r++) {
        vB[r] = *(const float4*)(bp[r]);
        *(uint2*)&sB[0][(brow + 32 * r) * SPH + bc4] = f4h(vB[r]);
    }
    CP_WAIT0();
    __syncthreads();

    const int NC = F / BK2;   // 64
    int cur = 0;
    for (int c = 0; c < NC; c++) {
        const int nxt = cur ^ 1;
        const bool more = (c + 1 < NC);
        if (more) {
            int k0 = (c + 1) * BK2;
#pragma unroll
            for (int i = 0; i < 2; i++) {
                int lin = i * 256 + tid;
                int row = lin >> 2, col8 = (lin & 3) * 8;
                cp_async16(&sA[nxt][row * SPH + col8], amb + (size_t)row * F + k0 + col8);
            }
            CP_COMMIT();
#pragma unroll
            for (int r = 0; r < 4; r++) vB[r] = *(const float4*)(bp[r] + k0);
        }

        // ---- compute on cur ----
#pragma unroll
        for (int kk = 0; kk < BK2; kk += 16) {
            unsigned a[2][4];
#pragma unroll
            for (int mt = 0; mt < 2; mt++)
                ldsm4(a[mt], &sA[cur][(wm + mt * 16 + (lane & 15)) * SPH + kk + (lane >> 4) * 8]);
            unsigned bf[4][4];
#pragma unroll
            for (int bh = 0; bh < 4; bh++) {
                int row = wn + bh * 16 + ((lane >> 4) & 1) * 8 + (lane & 7);
                int col = kk + ((lane >> 3) & 1) * 8;
                ldsm4(bf[bh], &sB[cur][row * SPH + col]);
            }
#pragma unroll
            for (int mt = 0; mt < 2; mt++)
#pragma unroll
                for (int nt = 0; nt < 8; nt++) {
                    int bh = nt >> 1, pr = (nt & 1) * 2;
                    mma16(acc[mt][nt], a[mt], bf[bh][pr], bf[bh][pr + 1]);
                }
        }

        if (more) {
#pragma unroll
            for (int r = 0; r < 4; r++)
                *(uint2*)&sB[nxt][(brow + 32 * r) * SPH + bc4] = f4h(vB[r]);
            CP_WAIT0();
            __syncthreads();
            cur = nxt;
        }
    }

    // ---- epilogue: weighted atomic scatter ----
    const int g = lane >> 2, tg = lane & 3;
#pragma unroll
    for (int mt = 0; mt < 2; mt++)
#pragma unroll
        for (int half = 0; half < 2; half++) {
            int m = m0 + wm + mt * 16 + g + half * 8;
            if (m >= ne) continue;
            int   tok = g_tok[e * T + m];
            float w   = g_wgt[e * T + m];
            float* dst = out + (size_t)tok * H + n0 + wn;
#pragma unroll
            for (int nt = 0; nt < 8; nt++) {
                atomicAdd(dst + nt * 8 + tg * 2 + 0, w * acc[mt][nt][half * 2 + 0]);
                atomicAdd(dst + nt * 8 + tg * 2 + 1, w * acc[mt][nt][half * 2 + 1]);
            }
        }
}

// ---------------------------------------------------------------
extern "C" void kernel_launch(void* const* d_in, const int* in_sizes, int n_in,
                              void* d_out, int out_size)
{
    const float* x  = (const float*)d_in[0];
    const float* gw = (const float*)d_in[1];
    const float* w1 = (const float*)d_in[2];
    const float* w2 = (const float*)d_in[3];
    const float* w3 = (const float*)d_in[4];
    float* out = (float*)d_out;

    const size_t main_sz = (size_t)T * H;
    float* logits = ((size_t)out_size >= main_sz + (size_t)T * E)
                        ? out + main_sz : nullptr;

    cudaMemsetAsync(d_out, 0, (size_t)out_size * sizeof(float));
    zero_cnt_kernel<<<1, 32>>>();
    xconv_kernel<<<(T * H) / (256 * 8), 256>>>(x);
    router_kernel<<<T / 8, 256>>>(x, gw, logits);
    gemm1_kernel<<<dim3(F / BN, T / BM, E), 256>>>(w1, w3);
    gemm2_kernel<<<dim3(H / BN2, T / BM2, E), 256>>>(w2, out);
}

// round 9
// speedup vs baseline: 1.4007x; 1.0220x over previous
#include <cuda_runtime.h>
#include <cuda_fp16.h>
#include <math.h>
#include <stdint.h>

#define H 1024
#define F 2048
#define E 8
#define T 2048

#define BM 128
#define BN 64
#define BK 32
#define BM2 128
#define BN2 128
#define BK2 32
#define SPH 40            // smem row stride (halfs) = 80B, 16B-aligned, ldmatrix conflict-free
#define NSTG 3

// gemm1 smem (halfs): A[3][128*40], B1[3][64*40], B3[3][64*40]
#define G1_AST (BM * SPH)
#define G1_BST (BN * SPH)
#define G1_A(s)  ((s) * G1_AST)
#define G1_B1(s) (NSTG * G1_AST + (s) * G1_BST)
#define G1_B3(s) (NSTG * G1_AST + NSTG * G1_BST + (s) * G1_BST)
#define G1_BYTES ((NSTG * G1_AST + 2 * NSTG * G1_BST) * 2)   // 61440
// gemm2 smem (halfs): A[3][128*40], B[3][128*40]
#define G2_AST (BM2 * SPH)
#define G2_A(s)  ((s) * G2_AST)
#define G2_B(s)  (NSTG * G2_AST + (s) * G2_AST)
#define G2_BYTES ((2 * NSTG * G2_AST) * 2)                   // 61440

// ---- scratch ----
__device__ int    g_cnt[E];
__device__ int    g_tok[E * T];
__device__ float  g_wgt[E * T];
__device__ __half g_x16[(size_t)T * H];
__device__ __half g_mid[(size_t)E * T * F];

// ---------------------------------------------------------------
__device__ __forceinline__ void ldsm4(unsigned r[4], const __half* p) {
    unsigned a = (unsigned)__cvta_generic_to_shared(p);
    asm volatile("ldmatrix.sync.aligned.m8n8.x4.shared.b16 {%0,%1,%2,%3}, [%4];"
                 : "=r"(r[0]), "=r"(r[1]), "=r"(r[2]), "=r"(r[3]) : "r"(a));
}
__device__ __forceinline__ void mma16(float c[4], const unsigned a[4], unsigned b0, unsigned b1) {
    asm volatile(
        "mma.sync.aligned.m16n8k16.row.col.f32.f16.f16.f32 "
        "{%0,%1,%2,%3},{%4,%5,%6,%7},{%8,%9},{%0,%1,%2,%3};"
        : "+f"(c[0]), "+f"(c[1]), "+f"(c[2]), "+f"(c[3])
        : "r"(a[0]), "r"(a[1]), "r"(a[2]), "r"(a[3]), "r"(b0), "r"(b1));
}
__device__ __forceinline__ uint2 f4h(float4 v) {
    __half2 lo = __floats2half2_rn(v.x, v.y);
    __half2 hi = __floats2half2_rn(v.z, v.w);
    uint2 r;
    r.x = *(unsigned*)&lo; r.y = *(unsigned*)&hi;
    return r;
}
__device__ __forceinline__ void cp_async16(const __half* sdst, const __half* gsrc) {
    unsigned d = (unsigned)__cvta_generic_to_shared(sdst);
    asm volatile("cp.async.cg.shared.global [%0], [%1], 16;" :: "r"(d), "l"(gsrc));
}
#define CP_COMMIT() asm volatile("cp.async.commit_group;" ::: "memory")
#define CP_WAIT0()  asm volatile("cp.async.wait_group 0;" ::: "memory")
#define CP_WAIT1()  asm volatile("cp.async.wait_group 1;" ::: "memory")

// ---------------------------------------------------------------
__global__ void zero_cnt_kernel() {
    if (threadIdx.x < E) g_cnt[threadIdx.x] = 0;
}

// ---------------------------------------------------------------
// Router (fused with x fp32->fp16 conversion): one warp per token.
__global__ __launch_bounds__(256) void router_kernel(
    const float* __restrict__ x, const float* __restrict__ gw,
    float* __restrict__ logits_out)
{
    const int t    = blockIdx.x * 8 + (threadIdx.x >> 5);
    const int lane = threadIdx.x & 31;
    const float4* xr  = (const float4*)(x + (size_t)t * H);
    const float4* gw4 = (const float4*)gw;
    __half* xo = g_x16 + (size_t)t * H;

    float acc[E];
#pragma unroll
    for (int e = 0; e < E; e++) acc[e] = 0.f;

#pragma unroll
    for (int i = 0; i < 8; i++) {
        float4 xv = xr[i * 32 + lane];
        *(uint2*)(xo + (i * 32 + lane) * 4) = f4h(xv);   // fp16 copy
#pragma unroll
        for (int e = 0; e < E; e++) {
            float4 g = gw4[e * 256 + i * 32 + lane];
            acc[e] += xv.x * g.x + xv.y * g.y + xv.z * g.z + xv.w * g.w;
        }
    }
#pragma unroll
    for (int e = 0; e < E; e++)
#pragma unroll
        for (int o = 16; o > 0; o >>= 1)
            acc[e] += __shfl_xor_sync(0xffffffffu, acc[e], o);

    if (lane == 0) {
        if (logits_out)
#pragma unroll
            for (int e = 0; e < E; e++) logits_out[(size_t)t * E + e] = acc[e];
        int i1 = 0;
#pragma unroll
        for (int e = 1; e < E; e++) if (acc[e] > acc[i1]) i1 = e;
        int i2 = -1;
#pragma unroll
        for (int e = 0; e < E; e++) {
            if (e == i1) continue;
            if (i2 < 0 || acc[e] > acc[i2]) i2 = e;
        }
        float wa = 1.f / (1.f + expf(acc[i2] - acc[i1]));
        float wb = 1.f - wa;
        int s1 = atomicAdd(&g_cnt[i1], 1);
        g_tok[i1 * T + s1] = t; g_wgt[i1 * T + s1] = wa;
        int s2 = atomicAdd(&g_cnt[i2], 1);
        g_tok[i2 * T + s2] = t; g_wgt[i2 * T + s2] = wb;
    }
}

// ---------------------------------------------------------------
// GEMM1 (fp16 mma, 3-stage): mid = silu(x.w1^T)*(x.w3^T) -> g_mid fp16.
__global__ __launch_bounds__(256, 2) void gemm1_kernel(
    const float* __restrict__ w1,
    const float* __restrict__ w3)
{
    extern __shared__ __align__(16) __half sm[];
    const int e  = blockIdx.z;
    const int n0 = blockIdx.x * BN;
    const int m0 = blockIdx.y * BM;
    const int ne = g_cnt[e];
    if (m0 >= ne) return;

    const int tid  = threadIdx.x;
    const int lane = tid & 31, wid = tid >> 5;
    const int wm   = (wid & 3) * 32, wn = (wid >> 2) * 32;

    // A loader (cp.async, 2 granules/thread): rows arow, arow+64; col8 slot
    const int arow = tid >> 2, ac8 = (tid & 3) * 8;
    const __half* amp0;
    const __half* amp1;
    {
        int m0r = m0 + arow, m1r = m0 + arow + 64;
        int i0 = (m0r < ne) ? m0r : (ne - 1);
        int i1 = (m1r < ne) ? m1r : (ne - 1);
        amp0 = g_x16 + (size_t)g_tok[e * T + i0] * H + ac8;
        amp1 = g_x16 + (size_t)g_tok[e * T + i1] * H + ac8;
    }
    // B loader: rows brow, brow+32; 4 floats per slot
    const int brow = tid >> 3, bc = (tid & 7) * 4;
    const float* b1p0 = w1 + ((size_t)e * F + n0 + brow) * H + bc;
    const float* b1p1 = b1p0 + 32 * H;
    const float* b3p0 = w3 + ((size_t)e * F + n0 + brow) * H + bc;
    const float* b3p1 = b3p0 + 32 * H;

    float4 vb1[2], vb3[2];
    float acc1[2][4][4] = {}, acc3[2][4][4] = {};

    const int NC = H / BK;   // 32

    // ---- prologue: A(c0), A(c1) in flight; B(c0) stored; B(c1) in regs ----
    cp_async16(&sm[G1_A(0) + arow * SPH + ac8],        amp0);
    cp_async16(&sm[G1_A(0) + (arow + 64) * SPH + ac8], amp1);
    CP_COMMIT();
    cp_async16(&sm[G1_A(1) + arow * SPH + ac8],        amp0 + BK);
    cp_async16(&sm[G1_A(1) + (arow + 64) * SPH + ac8], amp1 + BK);
    CP_COMMIT();
    vb1[0] = *(const float4*)(b1p0); vb1[1] = *(const float4*)(b1p1);
    vb3[0] = *(const float4*)(b3p0); vb3[1] = *(const float4*)(b3p1);
    *(uint2*)&sm[G1_B1(0) + brow * SPH + bc]        = f4h(vb1[0]);
    *(uint2*)&sm[G1_B1(0) + (brow + 32) * SPH + bc] = f4h(vb1[1]);
    *(uint2*)&sm[G1_B3(0) + brow * SPH + bc]        = f4h(vb3[0]);
    *(uint2*)&sm[G1_B3(0) + (brow + 32) * SPH + bc] = f4h(vb3[1]);
    vb1[0] = *(const float4*)(b1p0 + BK); vb1[1] = *(const float4*)(b1p1 + BK);
    vb3[0] = *(const float4*)(b3p0 + BK); vb3[1] = *(const float4*)(b3p1 + BK);
    CP_WAIT1();
    __syncthreads();

    int cur = 0;
    for (int c = 0; c < NC; c++) {
        const int nxt = (cur + 1 == NSTG) ? 0 : cur + 1;
        const int nx2 = (nxt + 1 == NSTG) ? 0 : nxt + 1;
        const bool have2 = (c + 2 < NC);

        if (have2) {
            int k2 = (c + 2) * BK;
            cp_async16(&sm[G1_A(nx2) + arow * SPH + ac8],        amp0 + k2);
            cp_async16(&sm[G1_A(nx2) + (arow + 64) * SPH + ac8], amp1 + k2);
            CP_COMMIT();
        }

        // ---- compute on cur ----
#pragma unroll
        for (int kk = 0; kk < BK; kk += 16) {
            unsigned a[2][4];
#pragma unroll
            for (int mt = 0; mt < 2; mt++)
                ldsm4(a[mt], &sm[G1_A(cur) + (wm + mt * 16 + (lane & 15)) * SPH + kk + (lane >> 4) * 8]);
            unsigned b1f[2][4], b3f[2][4];
#pragma unroll
            for (int bh = 0; bh < 2; bh++) {
                int row = wn + bh * 16 + ((lane >> 4) & 1) * 8 + (lane & 7);
                int col = kk + ((lane >> 3) & 1) * 8;
                ldsm4(b1f[bh], &sm[G1_B1(cur) + row * SPH + col]);
                ldsm4(b3f[bh], &sm[G1_B3(cur) + row * SPH + col]);
            }
#pragma unroll
            for (int mt = 0; mt < 2; mt++)
#pragma unroll
                for (int nt = 0; nt < 4; nt++) {
                    int bh = nt >> 1, pr = (nt & 1) * 2;
                    mma16(acc1[mt][nt], a[mt], b1f[bh][pr], b1f[bh][pr + 1]);
                    mma16(acc3[mt][nt], a[mt], b3f[bh][pr], b3f[bh][pr + 1]);
                }
        }

        if (c + 1 < NC) {
            // store B(c+1) from regs
            *(uint2*)&sm[G1_B1(nxt) + brow * SPH + bc]        = f4h(vb1[0]);
            *(uint2*)&sm[G1_B1(nxt) + (brow + 32) * SPH + bc] = f4h(vb1[1]);
            *(uint2*)&sm[G1_B3(nxt) + brow * SPH + bc]        = f4h(vb3[0]);
            *(uint2*)&sm[G1_B3(nxt) + (brow + 32) * SPH + bc] = f4h(vb3[1]);
            if (have2) {
                int k2 = (c + 2) * BK;
                vb1[0] = *(const float4*)(b1p0 + k2); vb1[1] = *(const float4*)(b1p1 + k2);
                vb3[0] = *(const float4*)(b3p0 + k2); vb3[1] = *(const float4*)(b3p1 + k2);
                CP_WAIT1();
            } else {
                CP_WAIT0();
            }
            __syncthreads();
            cur = nxt;
        }
    }

    // ---- epilogue: SwiGLU -> g_mid (fp16) ----
    const int g = lane >> 2, tg = lane & 3;
#pragma unroll
    for (int mt = 0; mt < 2; mt++)
#pragma unroll
        for (int half = 0; half < 2; half++) {
            int m = m0 + wm + mt * 16 + g + half * 8;
            if (m >= ne) continue;
            __half* dst = g_mid + ((size_t)e * T + m) * F + n0 + wn;
#pragma unroll
            for (int nt = 0; nt < 4; nt++) {
                float h0 = acc1[mt][nt][half * 2 + 0];
                float h1 = acc1[mt][nt][half * 2 + 1];
                float g0 = acc3[mt][nt][half * 2 + 0];
                float g1 = acc3[mt][nt][half * 2 + 1];
                float r0 = h0 / (1.f + __expf(-h0)) * g0;
                float r1 = h1 / (1.f + __expf(-h1)) * g1;
                *(__half2*)(dst + nt * 8 + tg * 2) = __floats2half2_rn(r0, r1);
            }
        }
}

// ---------------------------------------------------------------
// GEMM2 (fp16 mma, 3-stage): out[tok] += weight * (mid . w2^T)
__global__ __launch_bounds__(256, 2) void gemm2_kernel(
    const float* __restrict__ w2,
    float* __restrict__ out)
{
    extern __shared__ __align__(16) __half sm[];
    const int e  = blockIdx.z;
    const int n0 = blockIdx.x * BN2;
    const int m0 = blockIdx.y * BM2;
    const int ne = g_cnt[e];
    if (m0 >= ne) return;

    const int tid  = threadIdx.x;
    const int lane = tid & 31, wid = tid >> 5;
    const int wm   = (wid & 3) * 32, wn = (wid >> 2) * 64;

    const __half* amb = g_mid + ((size_t)e * T + m0) * F;
    // A loader: 2 granules/thread: row = tid>>2 (+64), col8 = (tid&3)*8
    const int arow = tid >> 2, ac8 = (tid & 3) * 8;
    const __half* amp0 = amb + (size_t)arow * F + ac8;
    const __half* amp1 = amb + (size_t)(arow + 64) * F + ac8;

    const int brow = tid >> 3, bc4 = (tid & 7) * 4;
    const float* bp[4];
#pragma unroll
    for (int r = 0; r < 4; r++)
        bp[r] = w2 + ((size_t)e * H + n0 + brow + 32 * r) * F + bc4;

    float acc[2][8][4] = {};
    float4 vB[4];

    const int NC = F / BK2;   // 64

    // ---- prologue ----
    cp_async16(&sm[G2_A(0) + arow * SPH + ac8],        amp0);
    cp_async16(&sm[G2_A(0) + (arow + 64) * SPH + ac8], amp1);
    CP_COMMIT();
    cp_async16(&sm[G2_A(1) + arow * SPH + ac8],        amp0 + BK2);
    cp_async16(&sm[G2_A(1) + (arow + 64) * SPH + ac8], amp1 + BK2);
    CP_COMMIT();
#pragma unroll
    for (int r = 0; r < 4; r++) {
        vB[r] = *(const float4*)(bp[r]);
        *(uint2*)&sm[G2_B(0) + (brow + 32 * r) * SPH + bc4] = f4h(vB[r]);
    }
#pragma unroll
    for (int r = 0; r < 4; r++) vB[r] = *(const float4*)(bp[r] + BK2);
    CP_WAIT1();
    __syncthreads();

    int cur = 0;
    for (int c = 0; c < NC; c++) {
        const int nxt = (cur + 1 == NSTG) ? 0 : cur + 1;
        const int nx2 = (nxt + 1 == NSTG) ? 0 : nxt + 1;
        const bool have2 = (c + 2 < NC);

        if (have2) {
            int k2 = (c + 2) * BK2;
            cp_async16(&sm[G2_A(nx2) + arow * SPH + ac8],        amp0 + k2);
            cp_async16(&sm[G2_A(nx2) + (arow + 64) * SPH + ac8], amp1 + k2);
            CP_COMMIT();
        }

        // ---- compute on cur ----
#pragma unroll
        for (int kk = 0; kk < BK2; kk += 16) {
            unsigned a[2][4];
#pragma unroll
            for (int mt = 0; mt < 2; mt++)
                ldsm4(a[mt], &sm[G2_A(cur) + (wm + mt * 16 + (lane & 15)) * SPH + kk + (lane >> 4) * 8]);
            unsigned bf[4][4];
#pragma unroll
            for (int bh = 0; bh < 4; bh++) {
                int row = wn + bh * 16 + ((lane >> 4) & 1) * 8 + (lane & 7);
                int col = kk + ((lane >> 3) & 1) * 8;
                ldsm4(bf[bh], &sm[G2_B(cur) + row * SPH + col]);
            }
#pragma unroll
            for (int mt = 0; mt < 2; mt++)
#pragma unroll
                for (int nt = 0; nt < 8; nt++) {
                    int bh = nt >> 1, pr = (nt & 1) * 2;
                    mma16(acc[mt][nt], a[mt], bf[bh][pr], bf[bh][pr + 1]);
                }
        }

        if (c + 1 < NC) {
#pragma unroll
            for (int r = 0; r < 4; r++)
                *(uint2*)&sm[G2_B(nxt) + (brow + 32 * r) * SPH + bc4] = f4h(vB[r]);
            if (have2) {
                int k2 = (c + 2) * BK2;
#pragma unroll
                for (int r = 0; r < 4; r++) vB[r] = *(const float4*)(bp[r] + k2);
                CP_WAIT1();
            } else {
                CP_WAIT0();
            }
            __syncthreads();
            cur = nxt;
        }
    }

    // ---- epilogue: weighted atomic scatter ----
    const int g = lane >> 2, tg = lane & 3;
#pragma unroll
    for (int mt = 0; mt < 2; mt++)
#pragma unroll
        for (int half = 0; half < 2; half++) {
            int m = m0 + wm + mt * 16 + g + half * 8;
            if (m >= ne) continue;
            int   tok = g_tok[e * T + m];
            float w   = g_wgt[e * T + m];
            float* dst = out + (size_t)tok * H + n0 + wn;
#pragma unroll
            for (int nt = 0; nt < 8; nt++) {
                atomicAdd(dst + nt * 8 + tg * 2 + 0, w * acc[mt][nt][half * 2 + 0]);
                atomicAdd(dst + nt * 8 + tg * 2 + 1, w * acc[mt][nt][half * 2 + 1]);
            }
        }
}

// ---------------------------------------------------------------
extern "C" void kernel_launch(void* const* d_in, const int* in_sizes, int n_in,
                              void* d_out, int out_size)
{
    const float* x  = (const float*)d_in[0];
    const float* gw = (const float*)d_in[1];
    const float* w1 = (const float*)d_in[2];
    const float* w2 = (const float*)d_in[3];
    const float* w3 = (const float*)d_in[4];
    float* out = (float*)d_out;

    static int configured = 0;
    if (!configured) {
        cudaFuncSetAttribute(gemm1_kernel,
            cudaFuncAttributeMaxDynamicSharedMemorySize, G1_BYTES);
        cudaFuncSetAttribute(gemm2_kernel,
            cudaFuncAttributeMaxDynamicSharedMemorySize, G2_BYTES);
        configured = 1;
    }

    const size_t main_sz = (size_t)T * H;
    float* logits = ((size_t)out_size >= main_sz + (size_t)T * E)
                        ? out + main_sz : nullptr;

    cudaMemsetAsync(d_out, 0, (size_t)out_size * sizeof(float));
    zero_cnt_kernel<<<1, 32>>>();
    router_kernel<<<T / 8, 256>>>(x, gw, logits);
    gemm1_kernel<<<dim3(F / BN, T / BM, E), 256, G1_BYTES>>>(w1, w3);
    gemm2_kernel<<<dim3(H / BN2, T / BM2, E), 256, G2_BYTES>>>(w2, out);
}